// round 1
// baseline (speedup 1.0000x reference)
#include <cuda_runtime.h>
#include <cstdint>

#define NTOK 16384
#define DIM  512
#define NEXP 8
#define HID  1024
#define NSLOT (NTOK*2)
#define MAXTILES (NSLOT/128 + NEXP)   // 264

// ---------------- device-global scratch (no allocs allowed) ----------------
__device__ float g_probsum[NEXP];
__device__ int   g_count[NEXP];
__device__ int   g_cursor[NEXP];
__device__ int   g_off[NEXP+1];
__device__ int   g_tile_e[MAXTILES];
__device__ int   g_tile_r0[MAXTILES];
__device__ int   g_tile_cnt[MAXTILES];
__device__ int   g_ntiles;
__device__ int   g_tok[NSLOT];          // slot -> token
__device__ int   g_eidx[NTOK*2];        // token -> (e0,e1)
__device__ int   g_slot[NTOK*2];        // token -> (slot0,slot1)
__device__ float g_w[NTOK*2];           // token -> (w0,w1)
__device__ float g_Hbuf[(size_t)NSLOT*HID];   // 134 MB
__device__ float g_Obuf[(size_t)NSLOT*DIM];   //  67 MB

// ---------------- small PTX helpers ----------------
__device__ __forceinline__ unsigned long long fma2_(unsigned long long a, unsigned long long b, unsigned long long c){
    asm("fma.rn.f32x2 %0, %1, %2, %3;" : "=l"(c) : "l"(a), "l"(b), "l"(c));
    return c;
}
__device__ __forceinline__ unsigned long long bcast2_(float v){
    unsigned long long r; asm("mov.b64 %0, {%1, %2};" : "=l"(r) : "f"(v), "f"(v)); return r;
}
#define CP16(dst, src) asm volatile("cp.async.cg.shared.global [%0], [%1], 16;\n" :: "r"(dst), "l"(src))
#define CPCOMMIT()     asm volatile("cp.async.commit_group;\n" ::: "memory")
#define CPWAIT(n)      asm volatile("cp.async.wait_group %0;\n" :: "n"(n) : "memory")

// ---------------- init ----------------
__global__ void init_kernel(){
    int t = threadIdx.x;
    if (t < NEXP){ g_probsum[t] = 0.f; g_count[t] = 0; }
}

// ---------------- router: logits, softmax, top-2, prob sums ----------------
__global__ void router_kernel(const float* __restrict__ x, const float* __restrict__ Wr,
                              const float* __restrict__ br){
    __shared__ float sWr[DIM*NEXP];
    __shared__ float sPs[NEXP];
    __shared__ int   sCnt[NEXP];
    int tid = threadIdx.x;
    for (int i = tid; i < DIM*NEXP; i += 256) sWr[i] = Wr[i];
    if (tid < NEXP){ sPs[tid] = 0.f; sCnt[tid] = 0; }
    __syncthreads();

    int warp = tid >> 5, lane = tid & 31;
    int t = blockIdx.x * 8 + warp;

    float acc[NEXP];
    #pragma unroll
    for (int e = 0; e < NEXP; e++) acc[e] = 0.f;
    const float* xr = x + (size_t)t * DIM;
    for (int d = lane; d < DIM; d += 32){
        float xv = xr[d];
        #pragma unroll
        for (int e = 0; e < NEXP; e++) acc[e] += xv * sWr[d*NEXP + e];
    }
    #pragma unroll
    for (int e = 0; e < NEXP; e++){
        #pragma unroll
        for (int o = 16; o > 0; o >>= 1) acc[e] += __shfl_xor_sync(0xffffffffu, acc[e], o);
    }
    if (lane == 0){
        float l[NEXP];
        float m = -1e30f;
        #pragma unroll
        for (int e = 0; e < NEXP; e++){ l[e] = acc[e] + br[e]; m = fmaxf(m, l[e]); }
        float s = 0.f;
        #pragma unroll
        for (int e = 0; e < NEXP; e++){ l[e] = expf(l[e] - m); s += l[e]; }
        float inv = 1.f / s;
        float p[NEXP];
        #pragma unroll
        for (int e = 0; e < NEXP; e++) p[e] = l[e] * inv;
        int i1 = 0;
        #pragma unroll
        for (int e = 1; e < NEXP; e++) if (p[e] > p[i1]) i1 = e;
        int i2 = (i1 == 0) ? 1 : 0;
        #pragma unroll
        for (int e = 0; e < NEXP; e++) if (e != i1 && p[e] > p[i2]) i2 = e;
        g_eidx[2*t] = i1; g_eidx[2*t+1] = i2;
        g_w[2*t] = p[i1]; g_w[2*t+1] = p[i2];
        #pragma unroll
        for (int e = 0; e < NEXP; e++) atomicAdd(&sPs[e], p[e]);
        atomicAdd(&sCnt[i1], 1); atomicAdd(&sCnt[i2], 1);
    }
    __syncthreads();
    if (tid < NEXP){
        atomicAdd(&g_probsum[tid], sPs[tid]);
        atomicAdd(&g_count[tid], sCnt[tid]);
    }
}

// ---------------- offsets, tile table, gating loss ----------------
__global__ void finalize_kernel(float* __restrict__ loss_out){
    if (threadIdx.x == 0){
        int off = 0;
        for (int e = 0; e < NEXP; e++){
            g_off[e] = off; g_cursor[e] = off; off += g_count[e];
        }
        g_off[NEXP] = off;
        int nt = 0;
        for (int e = 0; e < NEXP; e++){
            for (int r = g_off[e]; r < g_off[e+1]; r += 128){
                g_tile_e[nt] = e;
                g_tile_r0[nt] = r;
                int c = g_off[e+1] - r;
                g_tile_cnt[nt] = c < 128 ? c : 128;
                nt++;
            }
        }
        g_ntiles = nt;
        float lsum = 0.f;
        for (int e = 0; e < NEXP; e++){
            float mp = g_probsum[e] * (1.f/(float)NTOK);
            float d = (1.f/(float)NEXP) - mp;
            lsum += d*d;
        }
        *loss_out = (lsum / (float)NEXP) * 1e-4f;
    }
}

// ---------------- scatter: build slot permutation ----------------
__global__ void scatter_kernel(){
    int t = blockIdx.x * 256 + threadIdx.x;
    #pragma unroll
    for (int k = 0; k < 2; k++){
        int e = g_eidx[2*t + k];
        int s = atomicAdd(&g_cursor[e], 1);
        g_tok[s] = t;
        g_slot[2*t + k] = s;
    }
}

// ---------------- grouped FFN GEMM (fp32, f32x2 FMA, cp.async pipelined) ----
// MODE 0: C=g_Hbuf = leaky(gather(x) @ W1[e] + b1[e]),  K=512,  Ncols=1024
// MODE 1: C=g_Obuf = leaky(g_Hbuf   @ W2[e] + b2[e]),   K=1024, Ncols=512
template<int MODE>
__global__ __launch_bounds__(256, 2) void ffn_gemm(const float* __restrict__ Asrc,
                                                   const float* __restrict__ Bsrc,
                                                   const float* __restrict__ bias){
    constexpr int K     = (MODE == 0) ? DIM : HID;
    constexpr int NCOLS = (MODE == 0) ? HID : DIM;
    constexpr int KT    = K / 16;
    constexpr int GATHER = (MODE == 0);

    int bx = blockIdx.x;
    if (bx >= g_ntiles) return;
    int e   = g_tile_e[bx];
    int r0  = g_tile_r0[bx];
    int cnt = g_tile_cnt[bx];
    int n0  = blockIdx.y * 128;

    const float* A  = (MODE == 0) ? Asrc : g_Hbuf;
    float*       C  = (MODE == 0) ? g_Hbuf : g_Obuf;
    const float* Bp = Bsrc + (size_t)e * K * NCOLS;
    const float* biasp = bias + e * NCOLS;

    __shared__ float As[2][128][20];   // row-major, padded to 20 floats
    __shared__ float Bs[2][16][128];

    int tid = threadIdx.x;

    // prefetch source/dst mapping (fixed per thread)
    const float* aptr[2]; uint32_t adst[2];
    const float* bptr[2]; uint32_t bdst[2];
    #pragma unroll
    for (int i = 0; i < 2; i++){
        int v  = tid + i*256;          // 0..511
        int rl = v >> 2;               // 0..127
        int c4 = (v & 3) * 4;
        int rc = (rl < cnt) ? rl : 0;
        int grow = GATHER ? g_tok[r0 + rc] : (r0 + rc);
        aptr[i] = A + (size_t)grow * K + c4;
        adst[i] = (uint32_t)__cvta_generic_to_shared(&As[0][rl][c4]);
        int kr = v >> 5;               // 0..15
        int nn = (v & 31) * 4;         // 0..124
        bptr[i] = Bp + (size_t)kr * NCOLS + n0 + nn;
        bdst[i] = (uint32_t)__cvta_generic_to_shared(&Bs[0][kr][nn]);
    }
    const uint32_t ASTRIDE = sizeof(float)*128*20;
    const uint32_t BSTRIDE = sizeof(float)*16*128;

    // stage 0
    {
        #pragma unroll
        for (int i = 0; i < 2; i++) CP16(adst[i], aptr[i]);
        #pragma unroll
        for (int i = 0; i < 2; i++) CP16(bdst[i], bptr[i]);
        CPCOMMIT();
    }

    unsigned long long c2[8][4];
    #pragma unroll
    for (int i = 0; i < 8; i++)
        #pragma unroll
        for (int j = 0; j < 4; j++) c2[i][j] = 0ULL;

    int tm4 = (tid >> 4) * 4;
    int tn4 = (tid & 15) * 4;

    for (int kt = 0; kt < KT; kt++){
        int buf = kt & 1;
        if (kt + 1 < KT){
            size_t ka = (size_t)(kt+1) * 16;
            size_t kb = (size_t)(kt+1) * 16 * NCOLS;
            uint32_t so = (uint32_t)((buf^1) ? 1u : 0u);
            #pragma unroll
            for (int i = 0; i < 2; i++) CP16(adst[i] + so*ASTRIDE, aptr[i] + ka);
            #pragma unroll
            for (int i = 0; i < 2; i++) CP16(bdst[i] + so*BSTRIDE, bptr[i] + kb);
            CPCOMMIT();
            CPWAIT(1);
        } else {
            CPWAIT(0);
        }
        __syncthreads();

        #pragma unroll
        for (int k = 0; k < 16; k++){
            unsigned long long a2[8];
            #pragma unroll
            for (int i = 0; i < 4; i++){
                a2[i]   = bcast2_(As[buf][tm4 + i][k]);
                a2[4+i] = bcast2_(As[buf][64 + tm4 + i][k]);
            }
            ulonglong2 b0 = *reinterpret_cast<const ulonglong2*>(&Bs[buf][k][tn4]);
            ulonglong2 b1 = *reinterpret_cast<const ulonglong2*>(&Bs[buf][k][64 + tn4]);
            unsigned long long bb[4] = {b0.x, b0.y, b1.x, b1.y};
            #pragma unroll
            for (int i = 0; i < 8; i++)
                #pragma unroll
                for (int j = 0; j < 4; j++)
                    c2[i][j] = fma2_(a2[i], bb[j], c2[i][j]);
        }
        __syncthreads();
    }

    // epilogue: bias + LeakyReLU, guarded by expert row count
    #pragma unroll
    for (int i = 0; i < 8; i++){
        int ml = (i < 4) ? (tm4 + i) : (64 + tm4 + i - 4);
        if (ml >= cnt) continue;
        size_t rowoff = (size_t)(r0 + ml) * NCOLS;
        #pragma unroll
        for (int j = 0; j < 4; j++){
            float lo, hi;
            asm("mov.b64 {%0, %1}, %2;" : "=f"(lo), "=f"(hi) : "l"(c2[i][j]));
            int nl = (j < 2) ? (tn4 + j*2) : (64 + tn4 + (j-2)*2);
            int ng = n0 + nl;
            float v0 = lo + biasp[ng];
            float v1 = hi + biasp[ng+1];
            v0 = (v0 > 0.f) ? v0 : 0.01f * v0;
            v1 = (v1 > 0.f) ? v1 : 0.01f * v1;
            *reinterpret_cast<float2*>(&C[rowoff + ng]) = make_float2(v0, v1);
        }
    }
}

// ---------------- combine: out = w0*O[s0] + w1*O[s1] ----------------
__global__ void combine_kernel(float* __restrict__ out){
    int gid = blockIdx.x * 256 + threadIdx.x;    // over N*D/4
    int t = gid >> 7;                            // D/4 = 128 float4 per token
    int c = gid & 127;
    int s0 = g_slot[2*t], s1 = g_slot[2*t + 1];
    float w0 = g_w[2*t],  w1 = g_w[2*t + 1];
    const float4* O = reinterpret_cast<const float4*>(g_Obuf);
    float4 a = O[(size_t)s0 * 128 + c];
    float4 b = O[(size_t)s1 * 128 + c];
    float4 r;
    r.x = w0*a.x + w1*b.x;
    r.y = w0*a.y + w1*b.y;
    r.z = w0*a.z + w1*b.z;
    r.w = w0*a.w + w1*b.w;
    reinterpret_cast<float4*>(out)[gid] = r;
}

// ---------------- launch ----------------
extern "C" void kernel_launch(void* const* d_in, const int* in_sizes, int n_in,
                              void* d_out, int out_size){
    const float* x  = (const float*)d_in[0];
    const float* Wr = (const float*)d_in[1];
    const float* br = (const float*)d_in[2];
    const float* W1 = (const float*)d_in[3];
    const float* b1 = (const float*)d_in[4];
    const float* W2 = (const float*)d_in[5];
    const float* b2 = (const float*)d_in[6];
    float* out = (float*)d_out;

    init_kernel<<<1, 32>>>();
    router_kernel<<<NTOK/8, 256>>>(x, Wr, br);
    finalize_kernel<<<1, 32>>>(out + (out_size - 1));
    scatter_kernel<<<NTOK/256, 256>>>();
    ffn_gemm<0><<<dim3(MAXTILES, HID/128), 256>>>(x, W1, b1);
    ffn_gemm<1><<<dim3(MAXTILES, DIM/128), 256>>>(nullptr, W2, b2);
    combine_kernel<<<(NTOK*DIM/4)/256, 256>>>(out);
}

// round 3
// speedup vs baseline: 1.9957x; 1.9957x over previous
#include <cuda_runtime.h>
#include <cuda_bf16.h>
#include <cstdint>

#define NTOK 16384
#define DIM  512
#define NEXP 8
#define HID  1024
#define NSLOT (NTOK*2)
#define MAXTILES (NSLOT/128 + NEXP)   // 264

// ---------------- device-global scratch (no allocs allowed) ----------------
__device__ float g_probsum[NEXP];
__device__ int   g_count[NEXP];
__device__ int   g_cursor[NEXP];
__device__ int   g_off[NEXP+1];
__device__ int   g_tile_e[MAXTILES];
__device__ int   g_tile_r0[MAXTILES];
__device__ int   g_tile_cnt[MAXTILES];
__device__ int   g_ntiles;
__device__ int   g_tok[NSLOT];
__device__ int   g_eidx[NTOK*2];
__device__ int   g_slot[NTOK*2];
__device__ float g_w[NTOK*2];

__device__ __nv_bfloat16 g_xhi[(size_t)NTOK*DIM];
__device__ __nv_bfloat16 g_xlo[(size_t)NTOK*DIM];
__device__ __nv_bfloat16 g_w1t_hi[(size_t)NEXP*HID*DIM];  // [E][H][D] K-major
__device__ __nv_bfloat16 g_w1t_lo[(size_t)NEXP*HID*DIM];
__device__ __nv_bfloat16 g_w2t_hi[(size_t)NEXP*DIM*HID];  // [E][D][H] K-major
__device__ __nv_bfloat16 g_w2t_lo[(size_t)NEXP*DIM*HID];
__device__ __nv_bfloat16 g_Hhi[(size_t)NSLOT*HID];
__device__ __nv_bfloat16 g_Hlo[(size_t)NSLOT*HID];
__device__ float g_Obuf[(size_t)NSLOT*DIM];

// ---------------- PTX helpers ----------------
__device__ __forceinline__ uint32_t smem_u32(const void* p){
    uint32_t a;
    asm("{ .reg .u64 t; cvta.to.shared.u64 t, %1; cvt.u32.u64 %0, t; }" : "=r"(a) : "l"(p));
    return a;
}
#define CP16(dst, src) asm volatile("cp.async.cg.shared.global [%0], [%1], 16;\n" :: "r"(dst), "l"(src))
#define CPCOMMIT()     asm volatile("cp.async.commit_group;\n" ::: "memory")
#define CPWAIT(n)      asm volatile("cp.async.wait_group %0;\n" :: "n"(n) : "memory")
#define SWZ(o) ((o) ^ (((o) >> 3) & 0x70))

__device__ __forceinline__ void ldsm4(uint32_t* r, uint32_t addr){
    asm volatile("ldmatrix.sync.aligned.m8n8.x4.shared.b16 {%0,%1,%2,%3}, [%4];"
        : "=r"(r[0]), "=r"(r[1]), "=r"(r[2]), "=r"(r[3]) : "r"(addr));
}
__device__ __forceinline__ void hmma(float* d, const uint32_t* a, uint32_t b0, uint32_t b1){
    asm volatile("mma.sync.aligned.m16n8k16.row.col.f32.bf16.bf16.f32 "
        "{%0,%1,%2,%3}, {%4,%5,%6,%7}, {%8,%9}, {%0,%1,%2,%3};"
        : "+f"(d[0]), "+f"(d[1]), "+f"(d[2]), "+f"(d[3])
        : "r"(a[0]), "r"(a[1]), "r"(a[2]), "r"(a[3]), "r"(b0), "r"(b1));
}

// ---------------- init ----------------
__global__ void init_kernel(){
    int t = threadIdx.x;
    if (t < NEXP){ g_probsum[t] = 0.f; g_count[t] = 0; }
}

// ---------------- router ----------------
__global__ void router_kernel(const float* __restrict__ x, const float* __restrict__ Wr,
                              const float* __restrict__ br){
    __shared__ float sWr[DIM*NEXP];
    __shared__ float sPs[NEXP];
    __shared__ int   sCnt[NEXP];
    int tid = threadIdx.x;
    for (int i = tid; i < DIM*NEXP; i += 256) sWr[i] = Wr[i];
    if (tid < NEXP){ sPs[tid] = 0.f; sCnt[tid] = 0; }
    __syncthreads();

    int warp = tid >> 5, lane = tid & 31;
    int t = blockIdx.x * 8 + warp;

    float acc[NEXP];
    #pragma unroll
    for (int e = 0; e < NEXP; e++) acc[e] = 0.f;
    const float* xr = x + (size_t)t * DIM;
    for (int d = lane; d < DIM; d += 32){
        float xv = xr[d];
        #pragma unroll
        for (int e = 0; e < NEXP; e++) acc[e] += xv * sWr[d*NEXP + e];
    }
    #pragma unroll
    for (int e = 0; e < NEXP; e++){
        #pragma unroll
        for (int o = 16; o > 0; o >>= 1) acc[e] += __shfl_xor_sync(0xffffffffu, acc[e], o);
    }
    if (lane == 0){
        float l[NEXP];
        float m = -1e30f;
        #pragma unroll
        for (int e = 0; e < NEXP; e++){ l[e] = acc[e] + br[e]; m = fmaxf(m, l[e]); }
        float s = 0.f;
        #pragma unroll
        for (int e = 0; e < NEXP; e++){ l[e] = expf(l[e] - m); s += l[e]; }
        float inv = 1.f / s;
        float p[NEXP];
        #pragma unroll
        for (int e = 0; e < NEXP; e++) p[e] = l[e] * inv;
        int i1 = 0;
        #pragma unroll
        for (int e = 1; e < NEXP; e++) if (p[e] > p[i1]) i1 = e;
        int i2 = (i1 == 0) ? 1 : 0;
        #pragma unroll
        for (int e = 0; e < NEXP; e++) if (e != i1 && p[e] > p[i2]) i2 = e;
        g_eidx[2*t] = i1; g_eidx[2*t+1] = i2;
        g_w[2*t] = p[i1]; g_w[2*t+1] = p[i2];
        #pragma unroll
        for (int e = 0; e < NEXP; e++) atomicAdd(&sPs[e], p[e]);
        atomicAdd(&sCnt[i1], 1); atomicAdd(&sCnt[i2], 1);
    }
    __syncthreads();
    if (tid < NEXP){
        atomicAdd(&g_probsum[tid], sPs[tid]);
        atomicAdd(&g_count[tid], sCnt[tid]);
    }
}

// ---------------- finalize ----------------
__global__ void finalize_kernel(float* __restrict__ loss_out){
    if (threadIdx.x == 0){
        int off = 0;
        for (int e = 0; e < NEXP; e++){
            g_off[e] = off; g_cursor[e] = off; off += g_count[e];
        }
        g_off[NEXP] = off;
        int nt = 0;
        for (int e = 0; e < NEXP; e++){
            for (int r = g_off[e]; r < g_off[e+1]; r += 128){
                g_tile_e[nt] = e;
                g_tile_r0[nt] = r;
                int c = g_off[e+1] - r;
                g_tile_cnt[nt] = c < 128 ? c : 128;
                nt++;
            }
        }
        g_ntiles = nt;
        float lsum = 0.f;
        for (int e = 0; e < NEXP; e++){
            float mp = g_probsum[e] * (1.f/(float)NTOK);
            float d = (1.f/(float)NEXP) - mp;
            lsum += d*d;
        }
        *loss_out = (lsum / (float)NEXP) * 1e-4f;
    }
}

// ---------------- scatter ----------------
__global__ void scatter_kernel(){
    int t = blockIdx.x * 256 + threadIdx.x;
    #pragma unroll
    for (int k = 0; k < 2; k++){
        int e = g_eidx[2*t + k];
        int s = atomicAdd(&g_cursor[e], 1);
        g_tok[s] = t;
        g_slot[2*t + k] = s;
    }
}

// ---------------- convert x -> bf16 hi/lo ----------------
__global__ void convert_x_kernel(const float* __restrict__ x){
    int gid = blockIdx.x * 256 + threadIdx.x;    // NTOK*DIM/4 elems
    float4 v = reinterpret_cast<const float4*>(x)[gid];
    float f[4] = {v.x, v.y, v.z, v.w};
    __nv_bfloat16 h[4], l[4];
    #pragma unroll
    for (int i = 0; i < 4; i++){
        h[i] = __float2bfloat16_rn(f[i]);
        l[i] = __float2bfloat16_rn(f[i] - __bfloat162float(h[i]));
    }
    __nv_bfloat162 h0(h[0], h[1]), h1(h[2], h[3]), l0(l[0], l[1]), l1(l[2], l[3]);
    uint2 hp = make_uint2(*reinterpret_cast<uint32_t*>(&h0), *reinterpret_cast<uint32_t*>(&h1));
    uint2 lp = make_uint2(*reinterpret_cast<uint32_t*>(&l0), *reinterpret_cast<uint32_t*>(&l1));
    reinterpret_cast<uint2*>(g_xhi)[gid] = hp;
    reinterpret_cast<uint2*>(g_xlo)[gid] = lp;
}

// ---------------- transpose + convert weights: W[E][R][C] -> T[E][C][R] hi/lo --
template<int WID>   // 0: W1 (R=DIM,C=HID), 1: W2 (R=HID,C=DIM)
__global__ void convert_wT_kernel(const float* __restrict__ W){
    constexpr int R = (WID == 0) ? DIM : HID;
    constexpr int C = (WID == 0) ? HID : DIM;
    __nv_bfloat16* Thi = (WID == 0) ? g_w1t_hi : g_w2t_hi;
    __nv_bfloat16* Tlo = (WID == 0) ? g_w1t_lo : g_w2t_lo;
    __shared__ float ts[32][33];
    int e = blockIdx.z;
    int cb = blockIdx.x * 32, rb = blockIdx.y * 32;
    int tx = threadIdx.x & 31, ty = threadIdx.x >> 5;
    const float* Wp = W + (size_t)e * R * C;
    #pragma unroll
    for (int j = 0; j < 32; j += 8)
        ts[ty + j][tx] = Wp[(size_t)(rb + ty + j) * C + cb + tx];
    __syncthreads();
    size_t obase = (size_t)e * C * R;
    #pragma unroll
    for (int j = 0; j < 32; j += 8){
        float v = ts[tx][ty + j];
        __nv_bfloat16 h = __float2bfloat16_rn(v);
        __nv_bfloat16 lo = __float2bfloat16_rn(v - __bfloat162float(h));
        size_t o = obase + (size_t)(cb + ty + j) * R + rb + tx;
        Thi[o] = h; Tlo[o] = lo;
    }
}

// ---------------- HMMA grouped GEMM (bf16x3, 3-stage cp.async) ----------------
// MODE 0: H = leaky(gather(x) @ W1[e] + b1[e])  -> g_Hhi/g_Hlo,  K=512,  NCOLS=1024
// MODE 1: O = leaky(H @ W2[e] + b2[e])          -> g_Obuf,       K=1024, NCOLS=512
// smem stage layout (64 KB): [Ah 16K][Al 16K][Bh 16K][Bl 16K], rows of 128B (64 bf16),
// byte swizzle SWZ (xor 16B-unit by row&7) shared by cp.async stores and ldmatrix.
template<int MODE>
__global__ __launch_bounds__(256, 1) void ffn_gemm_mma(const float* __restrict__ bias){
    constexpr int K     = (MODE == 0) ? DIM : HID;
    constexpr int NCOLS = (MODE == 0) ? HID : DIM;
    constexpr int KT    = K / 64;

    int bx = blockIdx.x;
    if (bx >= g_ntiles) return;
    int e   = g_tile_e[bx];
    int r0  = g_tile_r0[bx];
    int cnt = g_tile_cnt[bx];
    int n0  = blockIdx.y * 128;
    int tid = threadIdx.x, wid = tid >> 5, lid = tid & 31;

    const __nv_bfloat16* Ah = (MODE == 0) ? g_xhi : g_Hhi;
    const __nv_bfloat16* Al = (MODE == 0) ? g_xlo : g_Hlo;
    const __nv_bfloat16* Bh = (MODE == 0) ? g_w1t_hi : g_w2t_hi;
    const __nv_bfloat16* Bl = (MODE == 0) ? g_w1t_lo : g_w2t_lo;
    const float* biasp = bias + e * NCOLS;

    extern __shared__ char dsm[];
    uint32_t sbase = smem_u32(dsm);

    // ---- loader mapping: 4 iters x 4 arrays, 16B each ----
    int ga[4], gb[4]; uint32_t dsw[4]; int s8[4];
    #pragma unroll
    for (int i = 0; i < 4; i++){
        int idx = i*256 + tid;
        int row = idx >> 3, sb = idx & 7;
        s8[i]  = sb * 8;
        dsw[i] = SWZ((uint32_t)(row*128 + sb*16));
        int ar = (row < cnt) ? row : (cnt - 1);
        ga[i]  = (MODE == 0) ? g_tok[r0 + ar] : (r0 + ar);
        gb[i]  = e * NCOLS + n0 + row;
    }
    auto load_chunk = [&](int kc, int bb){
        uint32_t base = sbase + (uint32_t)bb * 65536u;
        int koff = kc * 64;
        #pragma unroll
        for (int i = 0; i < 4; i++){
            size_t ao = (size_t)ga[i] * K + koff + s8[i];
            size_t bo = (size_t)gb[i] * K + koff + s8[i];
            CP16(base +         dsw[i], Ah + ao);
            CP16(base + 16384 + dsw[i], Al + ao);
            CP16(base + 32768 + dsw[i], Bh + bo);
            CP16(base + 49152 + dsw[i], Bl + bo);
        }
        CPCOMMIT();
    };

    // ---- per-lane ldmatrix addressing ----
    int wm = wid >> 1;                 // 0..3 -> m base wm*32
    int wn = wid & 1;                  // 0..1 -> n base wn*64
    uint32_t mask = (uint32_t)(lid & 7) << 4;
    uint32_t kx[4];
    #pragma unroll
    for (int ks = 0; ks < 4; ks++) kx[ks] = ((uint32_t)((lid >> 4)*16 + ks*32)) ^ mask;
    uint32_t arow[2], brow[4];
    #pragma unroll
    for (int mt = 0; mt < 2; mt++) arow[mt] = (uint32_t)((wm*32 + mt*16 + (lid & 15)) * 128);
    #pragma unroll
    for (int nt = 0; nt < 4; nt++) brow[nt] = (uint32_t)((wn*64 + nt*16 + (lid & 15)) * 128);

    float acc[2][8][4];
    #pragma unroll
    for (int mt = 0; mt < 2; mt++)
        #pragma unroll
        for (int j = 0; j < 8; j++)
            #pragma unroll
            for (int q = 0; q < 4; q++) acc[mt][j][q] = 0.f;

    load_chunk(0, 0);
    load_chunk(1, 1);

    for (int kt = 0; kt < KT; kt++){
        int b = kt % 3;
        if (kt < KT - 1) { CPWAIT(1); } else { CPWAIT(0); }
        __syncthreads();
        if (kt + 2 < KT) load_chunk(kt + 2, (kt + 2) % 3);

        uint32_t bAh = sbase + (uint32_t)b * 65536u;
        uint32_t bAl = bAh + 16384u;
        uint32_t bBh = bAh + 32768u;
        uint32_t bBl = bAh + 49152u;

        #pragma unroll
        for (int ks = 0; ks < 4; ks++){
            uint32_t ko = kx[ks];
            uint32_t ah[2][4], al[2][4], bh[4][4], bl[4][4];
            #pragma unroll
            for (int mt = 0; mt < 2; mt++){
                ldsm4(ah[mt], bAh + arow[mt] + ko);
                ldsm4(al[mt], bAl + arow[mt] + ko);
            }
            #pragma unroll
            for (int nt = 0; nt < 4; nt++){
                ldsm4(bh[nt], bBh + brow[nt] + ko);
                ldsm4(bl[nt], bBl + brow[nt] + ko);
            }
            #pragma unroll
            for (int mt = 0; mt < 2; mt++){
                #pragma unroll
                for (int j = 0; j < 8; j++){
                    int nt = j >> 1, s = j & 1;
                    hmma(acc[mt][j], ah[mt], bh[nt][s], bh[nt][s+2]);
                    hmma(acc[mt][j], ah[mt], bl[nt][s], bl[nt][s+2]);
                    hmma(acc[mt][j], al[mt], bh[nt][s], bh[nt][s+2]);
                }
            }
        }
        __syncthreads();
    }

    // ---- epilogue: bias + LeakyReLU, write C ----
    int mq = lid >> 2;          // 0..7
    int nq = (lid & 3) * 2;     // 0,2,4,6
    #pragma unroll
    for (int mt = 0; mt < 2; mt++){
        #pragma unroll
        for (int half = 0; half < 2; half++){
            int ml = wm*32 + mt*16 + half*8 + mq;
            if (ml >= cnt) continue;
            size_t orow = (size_t)(r0 + ml);
            #pragma unroll
            for (int j = 0; j < 8; j++){
                int ncol = n0 + wn*64 + j*8 + nq;
                float v0 = acc[mt][j][2*half]   + biasp[ncol];
                float v1 = acc[mt][j][2*half+1] + biasp[ncol+1];
                v0 = (v0 > 0.f) ? v0 : 0.01f*v0;
                v1 = (v1 > 0.f) ? v1 : 0.01f*v1;
                if (MODE == 0){
                    __nv_bfloat16 h0 = __float2bfloat16_rn(v0);
                    __nv_bfloat16 h1 = __float2bfloat16_rn(v1);
                    __nv_bfloat16 l0 = __float2bfloat16_rn(v0 - __bfloat162float(h0));
                    __nv_bfloat16 l1 = __float2bfloat16_rn(v1 - __bfloat162float(h1));
                    __nv_bfloat162 hh(h0, h1), ll(l0, l1);
                    *reinterpret_cast<uint32_t*>(&g_Hhi[orow*HID + ncol]) = *reinterpret_cast<uint32_t*>(&hh);
                    *reinterpret_cast<uint32_t*>(&g_Hlo[orow*HID + ncol]) = *reinterpret_cast<uint32_t*>(&ll);
                } else {
                    *reinterpret_cast<float2*>(&g_Obuf[orow*DIM + ncol]) = make_float2(v0, v1);
                }
            }
        }
    }
}

// ---------------- combine ----------------
__global__ void combine_kernel(float* __restrict__ out){
    int gid = blockIdx.x * 256 + threadIdx.x;
    int t = gid >> 7;
    int c = gid & 127;
    int s0 = g_slot[2*t], s1 = g_slot[2*t + 1];
    float w0 = g_w[2*t],  w1 = g_w[2*t + 1];
    const float4* O = reinterpret_cast<const float4*>(g_Obuf);
    float4 a = O[(size_t)s0 * 128 + c];
    float4 b = O[(size_t)s1 * 128 + c];
    float4 r;
    r.x = w0*a.x + w1*b.x;
    r.y = w0*a.y + w1*b.y;
    r.z = w0*a.z + w1*b.z;
    r.w = w0*a.w + w1*b.w;
    reinterpret_cast<float4*>(out)[gid] = r;
}

// ---------------- launch ----------------
extern "C" void kernel_launch(void* const* d_in, const int* in_sizes, int n_in,
                              void* d_out, int out_size){
    const float* x  = (const float*)d_in[0];
    const float* Wr = (const float*)d_in[1];
    const float* br = (const float*)d_in[2];
    const float* W1 = (const float*)d_in[3];
    const float* b1 = (const float*)d_in[4];
    const float* W2 = (const float*)d_in[5];
    const float* b2 = (const float*)d_in[6];
    float* out = (float*)d_out;

    const int SMEM_DYN = 3*65536;
    cudaFuncSetAttribute(ffn_gemm_mma<0>, cudaFuncAttributeMaxDynamicSharedMemorySize, SMEM_DYN);
    cudaFuncSetAttribute(ffn_gemm_mma<1>, cudaFuncAttributeMaxDynamicSharedMemorySize, SMEM_DYN);

    init_kernel<<<1, 32>>>();
    router_kernel<<<NTOK/8, 256>>>(x, Wr, br);
    finalize_kernel<<<1, 32>>>(out + (out_size - 1));
    scatter_kernel<<<NTOK/256, 256>>>();
    convert_x_kernel<<<(NTOK*DIM/4)/256, 256>>>(x);
    convert_wT_kernel<0><<<dim3(HID/32, DIM/32, NEXP), 256>>>(W1);
    convert_wT_kernel<1><<<dim3(DIM/32, HID/32, NEXP), 256>>>(W2);
    ffn_gemm_mma<0><<<dim3(MAXTILES, HID/128), 256, SMEM_DYN>>>(b1);
    ffn_gemm_mma<1><<<dim3(MAXTILES, DIM/128), 256, SMEM_DYN>>>(b2);
    combine_kernel<<<(NTOK*DIM/4)/256, 256>>>(out);
}